// round 14
// baseline (speedup 1.0000x reference)
#include <cuda_runtime.h>
#include <cuda_bf16.h>
#include <cstdint>

#define S        771                 // STATE
#define JP       832                 // padded states = 13*64
#define NB       32                  // batch
#define NT       128                 // time
#define NGR      4                   // clusters (4*13 = 52 SMs: fits one die)
#define MB       8                   // batches per group
#define NCG      13                  // CTAs per cluster
#define NCTA     (NGR*NCG)           // 52
#define WJ       64                  // j columns per CTA
#define NWARP    8
#define NTHR     256
#define KT       13                  // k-tiles (of 16) per k-quarter
#define ROWU     420                 // padded u32 row stride (mod 32 = 4: no LDS conflicts)
#define BUFB     (MB*ROWU*4)         // bytes per W buffer (13440)
#define NARRV    768                 // 12 peers x 64 chunk-arrivals
#define INV1024  (1.0f/1024.0f)
#define LSUM     880.2969192511308f  // 127 * ln(1024)

// ---------------- persistent device state ----------------
__device__ __align__(16) float g_EME[(size_t)NT * JP * NB]; // exp(em)/1024, [t][j][b]
__device__ unsigned g_scp[NCTA][NB];       // per-CTA score partials (f32 bits)
__device__ unsigned g_zfin[NB];            // per-batch final z-sums (f32 bits)
__device__ unsigned g_fin[NGR * 32];       // per-group done epochs (monotone)

static __device__ __forceinline__ uint32_t smem_u32(const void* p) {
    uint32_t a;
    asm("{ .reg .u64 t; cvta.to.shared.u64 t, %1; cvt.u32.u64 %0, t; }" : "=r"(a) : "l"(p));
    return a;
}
static __device__ __forceinline__ uint32_t pack_bf16x2(float lo, float hi) {
    uint32_t r;
    asm("cvt.rn.bf16x2.f32 %0,%1,%2;" : "=r"(r) : "f"(hi), "f"(lo));
    return r;
}
static __device__ __forceinline__ void mma16816(float* c, uint32_t a0, uint32_t a1,
                                                uint32_t a2, uint32_t a3,
                                                uint32_t b0, uint32_t b1) {
    asm volatile("mma.sync.aligned.m16n8k16.row.col.f32.bf16.bf16.f32 "
                 "{%0,%1,%2,%3},{%4,%5,%6,%7},{%8,%9},{%0,%1,%2,%3};"
                 : "+f"(c[0]), "+f"(c[1]), "+f"(c[2]), "+f"(c[3])
                 : "r"(a0), "r"(a1), "r"(a2), "r"(a3), "r"(b0), "r"(b1));
}
#define CLUSTER_SYNC() do { \
    asm volatile("barrier.cluster.arrive.aligned;" ::: "memory"); \
    asm volatile("barrier.cluster.wait.aligned;"   ::: "memory"); \
} while (0)
static __device__ __forceinline__ void st_rel(unsigned* p, unsigned v) {
    asm volatile("st.release.gpu.global.b32 [%0],%1;" :: "l"(p), "r"(v) : "memory");
}
static __device__ __forceinline__ unsigned ld_acq(const unsigned* p) {
    unsigned v;
    asm volatile("ld.acquire.gpu.global.b32 %0,[%1];" : "=r"(v) : "l"(p) : "memory");
    return v;
}
static __device__ __forceinline__ void st_cluster_v4(uint32_t addr, uint4 v) {
    asm volatile("st.shared::cluster.v4.u32 [%0], {%1,%2,%3,%4};"
                 :: "r"(addr), "r"(v.x), "r"(v.y), "r"(v.z), "r"(v.w) : "memory");
}
static __device__ __forceinline__ void mbar_arrive_remote(uint32_t addr) {
    asm volatile("mbarrier.arrive.release.cluster.shared::cluster.b64 _, [%0];"
                 :: "r"(addr) : "memory");
}
#define MBAR_WAIT(addr, ph) do { \
    uint32_t _m = (addr), _p = (uint32_t)(ph), _d; \
    asm volatile("{\n\t.reg .pred p;\n\t" \
        "mbarrier.try_wait.parity.acquire.cluster.shared::cta.b64 p, [%1], %2;\n\t" \
        "selp.b32 %0, 1, 0, p;\n\t}" : "=r"(_d) : "r"(_m), "r"(_p) : "memory"); \
    if (!_d) { \
        asm volatile("{\n\t.reg .pred P1;\n\t" \
            "WL_%=:\n\t" \
            "mbarrier.try_wait.parity.acquire.cluster.shared::cta.b64 P1, [%0], %1, 0x989680;\n\t" \
            "@P1 bra.uni WD_%=;\n\t" \
            "bra.uni WL_%=;\n\t" \
            "WD_%=:\n\t}" :: "r"(_m), "r"(_p) : "memory"); \
    } \
} while (0)

__global__ void __launch_bounds__(NTHR, 1)
crf_kernel(const float* __restrict__ em, const int* __restrict__ tags32,
           const float* __restrict__ mask, const float* __restrict__ trans,
           float* __restrict__ out)
{
    __shared__ __align__(16) uint32_t sW[2][MB][ROWU];   // group W replica, dbl-buf
    __shared__ __align__(16) float s_D[4][MB][WJ + 2];
    __shared__ __align__(8) unsigned long long mbar[2];  // one per W buffer

    const int tid  = threadIdx.x;
    const int w    = tid >> 5;
    const int lane = tid & 31;
    const int g    = lane >> 2;
    const int tg   = lane & 3;
    const int cta  = blockIdx.x;
    const int grp  = cta / NCG;
    const int cg   = cta % NCG;        // cluster ctarank
    const int j0   = cg * WJ;
    const int kq   = w & 3;
    const int nh   = w >> 2;
    const int kb0  = kq * (KT * 16);

    const int bl_e = tid >> 5;
    const int b_e  = grp * MB + bl_e;
    const int jp_e = tid & 31;
    const int jl_e = jp_e * 2;

    unsigned finbase = 0;
    if (cg == 0 && tid == 0) finbase = __ldcg(&g_fin[grp * 32]);

    // DSMEM remote bases
    const uint32_t sWb = smem_u32(&sW[0][0][0]);
    const uint32_t mbb = smem_u32(&mbar[0]);
    uint32_t rbase[NCG], rmbar[NCG];
    #pragma unroll
    for (int r = 0; r < NCG; r++) {
        asm("mapa.shared::cluster.u32 %0, %1, %2;" : "=r"(rbase[r]) : "r"(sWb), "r"(r));
        asm("mapa.shared::cluster.u32 %0, %1, %2;" : "=r"(rmbar[r]) : "r"(mbb), "r"(r));
    }
    // push assignments: 3 chunks/thread -> 12 peers x 64 16B-chunks
    int  p_rank[3]; uint32_t p_off[3];
    #pragma unroll
    for (int q = 0; q < 3; q++) {
        int a  = tid + q * NTHR;
        int rr = a >> 6;
        p_rank[q] = rr + (rr >= cg);
        int c  = a & 63;
        p_off[q] = (uint32_t)(((c >> 3) * ROWU + (j0 >> 1) + (c & 7) * 4) * 4);
    }

    // =============== INIT ===============
    if (tid == 0) {
        asm volatile("mbarrier.init.shared.b64 [%0], %1;" :: "r"(mbb),     "r"(NARRV) : "memory");
        asm volatile("mbarrier.init.shared.b64 [%0], %1;" :: "r"(mbb + 8), "r"(NARRV) : "memory");
    }
    // B fragments (E^T slice) in registers
    uint32_t bfr[KT][4][2];
    #pragma unroll
    for (int kt = 0; kt < KT; kt++) {
        #pragma unroll
        for (int nt = 0; nt < 4; nt++) {
            const int jg = j0 + nh * 32 + nt * 8 + g;
            #pragma unroll
            for (int r = 0; r < 2; r++) {
                const int i0 = kb0 + kt * 16 + 2 * tg + 8 * r;
                float lo = (i0     < S && jg < S) ? __expf(trans[(i0    ) * S + jg]) : 0.f;
                float hi = (i0 + 1 < S && jg < S) ? __expf(trans[(i0 + 1) * S + jg]) : 0.f;
                bfr[kt][nt][r] = pack_bf16x2(lo, hi);
            }
        }
    }
    // full W_0 replica (so step 1 needs no exchange)
    for (int idx = tid; idx < MB * (JP / 2); idx += NTHR) {
        int r = idx / (JP / 2), cu = idx % (JP / 2);
        int b = grp * MB + r, ja = 2 * cu, jb = ja + 1;
        float f0 = (ja < S) ? __expf(trans[ja] + em[(size_t)b * NT * S + ja]) : 0.f;
        float f1 = (jb < S) ? __expf(trans[jb] + em[(size_t)b * NT * S + jb]) : 0.f;
        sW[0][r][cu] = pack_bf16x2(f0, f1);
    }
    // EME[t][j][b] = exp(em[b,t,j])/1024 for own group's batches
    for (size_t id = (size_t)JP + (size_t)cg * NTHR + tid; id < (size_t)NT * JP;
         id += (size_t)NCG * NTHR) {
        int t = (int)(id / JP), j = (int)(id % JP);
        float4* dst = reinterpret_cast<float4*>(&g_EME[id * NB + grp * MB]);
        if (j < S) {
            #pragma unroll
            for (int q = 0; q < 2; q++) {
                const int b0 = grp * MB + q * 4;
                float4 v;
                v.x = __expf(em[((size_t)(b0 + 0) * NT + t) * S + j]) * INV1024;
                v.y = __expf(em[((size_t)(b0 + 1) * NT + t) * S + j]) * INV1024;
                v.z = __expf(em[((size_t)(b0 + 2) * NT + t) * S + j]) * INV1024;
                v.w = __expf(em[((size_t)(b0 + 3) * NT + t) * S + j]) * INV1024;
                dst[q] = v;
            }
        } else {
            float4 z = {0.f, 0.f, 0.f, 0.f};
            dst[0] = z; dst[1] = z;
        }
    }
    // score gather (warp 7; lane = batch)
    if (w == NWARP - 1) {
        const bool is64 = (tags32[1] == 0);
        const int b = lane;
        float sc = 0.f;
        for (int t = cta + 1; t < NT; t += NCTA) {
            float m = mask[b * NT + t];
            int cur = is64 ? tags32[(b * NT + t) * 2]     : tags32[b * NT + t];
            int prv = is64 ? tags32[(b * NT + t - 1) * 2] : tags32[b * NT + t - 1];
            sc += (em[((size_t)b * NT + t) * S + cur] + trans[prv * S + cur]) * m;
        }
        if (cta == NCTA - 1) {
            int tag0 = is64 ? tags32[(b * NT) * 2] : tags32[b * NT];
            sc += trans[tag0] + em[(size_t)b * NT * S + tag0];
            float ms = 0.f;
            for (int t = 0; t < NT; t++) ms += mask[b * NT + t];
            int li = (int)ms - 1;
            int lt = is64 ? tags32[(b * NT + li) * 2] : tags32[b * NT + li];
            sc += trans[lt * S + 1];
        }
        st_rel(&g_scp[cta][lane], __float_as_uint(sc));
    }
    __syncthreads();
    CLUSTER_SYNC();                            // mbarrier init visible cluster-wide

    const int kwof = (kb0 >> 1) + tg;
    const uint32_t zero = 0u;
    int p0 = 0, p1 = 0;                        // per-buffer phase parities

    float mk = mask[b_e * NT + 1];
    float e0 = g_EME[((size_t)1 * JP + j0 + jl_e) * NB + b_e];
    float e1 = g_EME[((size_t)1 * JP + j0 + jl_e + 1) * NB + b_e];

    // =============== MAIN LOOP: 127 dataflow GEMM steps ===============
    for (int t = 1; t < NT; ++t) {
        const int prev = (t - 1) & 1, cur = t & 1;

        if (t >= 2) {                          // wait for W_{t-1} slices (dataflow)
            if (prev == 0) { MBAR_WAIT(mbb,     p0); p0 ^= 1; }
            else           { MBAR_WAIT(mbb + 8, p1); p1 ^= 1; }
        }

        const uint32_t* aRow = &sW[prev][g][0];
        float c[4][4];
        #pragma unroll
        for (int nt = 0; nt < 4; nt++) { c[nt][0]=0.f; c[nt][1]=0.f; c[nt][2]=0.f; c[nt][3]=0.f; }
        #pragma unroll
        for (int kt = 0; kt < KT; kt++) {
            const int kw = kwof + kt * 8;
            uint32_t a0 = aRow[kw];
            uint32_t a2 = aRow[kw + 4];
            #pragma unroll
            for (int nt = 0; nt < 4; nt++)
                mma16816(c[nt], a0, zero, a2, zero, bfr[kt][nt][0], bfr[kt][nt][1]);
        }
        #pragma unroll
        for (int nt = 0; nt < 4; nt++) {
            float2* p = reinterpret_cast<float2*>(&s_D[kq][g][nh * 32 + nt * 8 + 2 * tg]);
            *p = make_float2(c[nt][0], c[nt][1]);
        }
        __syncthreads();

        // ---- epilogue: reduce, scale, pack; stage own slice locally ----
        {
            float s0 = 0.f, s1 = 0.f;
            #pragma unroll
            for (int q = 0; q < 4; q++) {
                s0 += s_D[q][bl_e][jl_e];
                s1 += s_D[q][bl_e][jl_e + 1];
            }
            float nv0 = s0 * e0, nv1 = s1 * e1;
            if (mk <= 0.f) {
                uint32_t old = sW[prev][bl_e][(j0 >> 1) + jp_e];
                nv0 = __uint_as_float(old << 16)         * INV1024;
                nv1 = __uint_as_float(old & 0xFFFF0000u) * INV1024;
            }
            sW[cur][bl_e][(j0 >> 1) + jp_e] = pack_bf16x2(nv0, nv1);
        }
        __syncthreads();                       // staging complete

        // ---- push 16B chunks to 12 peers + remote release-arrive ----
        {
            const uint32_t bofs = (uint32_t)cur * BUFB;
            const uint32_t mofs = (uint32_t)cur * 8u;
            #pragma unroll
            for (int q = 0; q < 3; q++) {
                uint4 v = *reinterpret_cast<const uint4*>(
                              reinterpret_cast<const char*>(sW) + bofs + p_off[q]);
                st_cluster_v4(rbase[p_rank[q]] + bofs + p_off[q], v);
            }
            #pragma unroll
            for (int q = 0; q < 3; q++)
                mbar_arrive_remote(rmbar[p_rank[q]] + mofs);
        }

        if (t + 1 < NT) {                      // prefetch next step's inputs
            mk = mask[b_e * NT + (t + 1)];
            e0 = g_EME[((size_t)(t + 1) * JP + j0 + jl_e) * NB + b_e];
            e1 = g_EME[((size_t)(t + 1) * JP + j0 + jl_e + 1) * NB + b_e];
        }
    }

    // =============== FINAL: per-group z, then CTA 0 reduces ===============
    if (cg == 0) {                             // leader: needs complete W_127 (buf 1)
        MBAR_WAIT(mbb + 8, p1);
        __syncthreads();
        if (w < MB) {
            float zp = 0.f;
            for (int cu = lane; cu < JP / 2; cu += 32) {
                uint32_t u = sW[1][w][cu];
                int ja = 2 * cu, jb = ja + 1;
                if (ja < S) zp += __uint_as_float(u << 16)         * __expf(trans[ja * S + 1]);
                if (jb < S) zp += __uint_as_float(u & 0xFFFF0000u) * __expf(trans[jb * S + 1]);
            }
            #pragma unroll
            for (int o = 16; o; o >>= 1) zp += __shfl_xor_sync(0xffffffffu, zp, o);
            if (lane == 0) st_rel(&g_zfin[grp * MB + w], __float_as_uint(zp));
        }
        __syncthreads();
        if (tid == 0) st_rel(&g_fin[grp * 32], finbase + 1u);
    }
    CLUSTER_SYNC();                            // no CTA exits with remote stores in flight

    if (cta == 0) {
        if (tid == 0) {
            for (int gg = 1; gg < NGR; gg++)
                while ((int)(ld_acq(&g_fin[gg * 32]) - (finbase + 1u)) < 0) { }
        }
        __syncthreads();
        if (w == 0) {
            const int b = lane;
            float zs = __uint_as_float(ld_acq(&g_zfin[b]));
            float sc = 0.f;
            for (int c2 = 0; c2 < NCTA; c2++)
                sc += __uint_as_float(ld_acq(&g_scp[c2][b]));
            float r = (logf(zs) + LSUM) - sc;
            #pragma unroll
            for (int o = 16; o; o >>= 1) r += __shfl_xor_sync(0xffffffffu, r, o);
            if (lane == 0) out[0] = r;         // NLL
        }
    }
}

extern "C" void kernel_launch(void* const* d_in, const int* in_sizes, int n_in,
                              void* d_out, int out_size)
{
    (void)in_sizes; (void)n_in; (void)out_size;
    const float* em    = (const float*)d_in[0];
    const int*   tags  = (const int*)  d_in[1];   // int64 or int32, detected in-kernel
    const float* mask  = (const float*)d_in[2];
    const float* trans = (const float*)d_in[3];
    float* o = (float*)d_out;

    cudaFuncSetAttribute(crf_kernel, cudaFuncAttributeNonPortableClusterSizeAllowed, 1);

    cudaLaunchConfig_t cfg = {};
    cfg.gridDim  = {NCTA, 1, 1};
    cfg.blockDim = {NTHR, 1, 1};
    cfg.dynamicSmemBytes = 0;
    cfg.stream = 0;
    cudaLaunchAttribute at[1];
    at[0].id = cudaLaunchAttributeClusterDimension;
    at[0].val.clusterDim = {NCG, 1, 1};
    cfg.attrs = at;
    cfg.numAttrs = 1;
    cudaLaunchKernelEx(&cfg, crf_kernel, em, tags, mask, trans, o);
}

// round 15
// speedup vs baseline: 1.5925x; 1.5925x over previous
#include <cuda_runtime.h>
#include <cuda_bf16.h>
#include <cstdint>

#define S        771                 // STATE
#define JP       832                 // padded states = 13*64
#define NB       32                  // batch
#define NT       128                 // time
#define NGR      4                   // clusters (4*13 = 52 SMs: fits one die)
#define MB       8                   // batches per group
#define NCG      13                  // CTAs per cluster
#define NCTA     (NGR*NCG)           // 52
#define WJ       64                  // j columns per CTA
#define NWARP    8
#define NTHR     256
#define KT       13                  // k-tiles (of 16) per k-quarter
#define SLOTU    36                  // u32 per row in a slice (32 data + 4 pad)
#define SLICEU   (MB*SLOTU)          // 288 u32 = 1152 B per CTA slice
#define SLICEB   (SLICEU*4)          // 1152
#define BUFU     (NCG*SLICEU)        // 3744 u32 per W buffer
#define BUFB     (BUFU*4)            // 14976 B
#define TXB      (12*SLICEB)         // 13824 expected bytes per phase
#define INV1024  (1.0f/1024.0f)
#define LSUM     880.2969192511308f  // 127 * ln(1024)

// ---------------- persistent device state ----------------
__device__ __align__(16) float g_EME[(size_t)NT * JP * NB]; // exp(em)/1024, [t][j][b]
__device__ unsigned g_scp[NCTA][NB];       // per-CTA score partials (f32 bits)
__device__ unsigned g_zfin[NB];            // per-batch final z-sums (f32 bits)
__device__ unsigned g_fin[NGR * 32];       // per-group done epochs (monotone)

static __device__ __forceinline__ uint32_t smem_u32(const void* p) {
    uint32_t a;
    asm("{ .reg .u64 t; cvta.to.shared.u64 t, %1; cvt.u32.u64 %0, t; }" : "=r"(a) : "l"(p));
    return a;
}
static __device__ __forceinline__ uint32_t pack_bf16x2(float lo, float hi) {
    uint32_t r;
    asm("cvt.rn.bf16x2.f32 %0,%1,%2;" : "=r"(r) : "f"(hi), "f"(lo));
    return r;
}
static __device__ __forceinline__ void mma16816(float* c, uint32_t a0, uint32_t a1,
                                                uint32_t a2, uint32_t a3,
                                                uint32_t b0, uint32_t b1) {
    asm volatile("mma.sync.aligned.m16n8k16.row.col.f32.bf16.bf16.f32 "
                 "{%0,%1,%2,%3},{%4,%5,%6,%7},{%8,%9},{%0,%1,%2,%3};"
                 : "+f"(c[0]), "+f"(c[1]), "+f"(c[2]), "+f"(c[3])
                 : "r"(a0), "r"(a1), "r"(a2), "r"(a3), "r"(b0), "r"(b1));
}
#define CLUSTER_SYNC() do { \
    asm volatile("barrier.cluster.arrive.aligned;" ::: "memory"); \
    asm volatile("barrier.cluster.wait.aligned;"   ::: "memory"); \
} while (0)
static __device__ __forceinline__ void st_rel(unsigned* p, unsigned v) {
    asm volatile("st.release.gpu.global.b32 [%0],%1;" :: "l"(p), "r"(v) : "memory");
}
static __device__ __forceinline__ unsigned ld_acq(const unsigned* p) {
    unsigned v;
    asm volatile("ld.acquire.gpu.global.b32 %0,[%1];" : "=r"(v) : "l"(p) : "memory");
    return v;
}
#define MBAR_EXPECT_TX(addr, bytes) \
    asm volatile("mbarrier.arrive.expect_tx.shared.b64 _, [%0], %1;" \
                 :: "r"(addr), "r"((uint32_t)(bytes)) : "memory")
#define MBAR_WAIT(addr, ph) do { \
    uint32_t _m = (addr), _p = (uint32_t)(ph), _d; \
    asm volatile("{\n\t.reg .pred p;\n\t" \
        "mbarrier.try_wait.parity.acquire.cta.shared::cta.b64 p, [%1], %2;\n\t" \
        "selp.b32 %0, 1, 0, p;\n\t}" : "=r"(_d) : "r"(_m), "r"(_p) : "memory"); \
    if (!_d) { \
        asm volatile("{\n\t.reg .pred P1;\n\t" \
            "WL_%=:\n\t" \
            "mbarrier.try_wait.parity.acquire.cta.shared::cta.b64 P1, [%0], %1, 0x989680;\n\t" \
            "@P1 bra.uni WD_%=;\n\t" \
            "bra.uni WL_%=;\n\t" \
            "WD_%=:\n\t}" :: "r"(_m), "r"(_p) : "memory"); \
    } \
} while (0)
static __device__ __forceinline__ void bulk_copy_cluster(uint32_t dst, uint32_t src,
                                                         uint32_t bytes, uint32_t mbar) {
    asm volatile("cp.async.bulk.shared::cluster.shared::cta.mbarrier::complete_tx::bytes "
                 "[%0], [%1], %2, [%3];"
                 :: "r"(dst), "r"(src), "r"(bytes), "r"(mbar) : "memory");
}

__global__ void __launch_bounds__(NTHR, 1)
crf_kernel(const float* __restrict__ em, const int* __restrict__ tags32,
           const float* __restrict__ mask, const float* __restrict__ trans,
           float* __restrict__ out)
{
    __shared__ __align__(16) uint32_t sWu[2 * BUFU];     // W replica, [buf][slice][row][36]
    __shared__ __align__(16) float s_D[4][MB][WJ + 2];
    __shared__ __align__(8) unsigned long long mbar[2];  // one per W buffer

    const int tid  = threadIdx.x;
    const int w    = tid >> 5;
    const int lane = tid & 31;
    const int g    = lane >> 2;        // MMA row within group (0..7 = MB)
    const int tg   = lane & 3;
    const int cta  = blockIdx.x;
    const int grp  = cta / NCG;
    const int cg   = cta % NCG;        // cluster ctarank
    const int j0   = cg * WJ;
    const int kq   = w & 3;
    const int nh   = w >> 2;
    const int kb0  = kq * (KT * 16);

    const int bl_e = tid >> 5;
    const int b_e  = grp * MB + bl_e;
    const int jp_e = tid & 31;
    const int jl_e = jp_e * 2;

    unsigned finbase = 0;
    if (cg == 0 && tid == 0) finbase = __ldcg(&g_fin[grp * 32]);

    // DSMEM remote bases
    const uint32_t sWb = smem_u32(&sWu[0]);
    const uint32_t mbb = smem_u32(&mbar[0]);
    uint32_t rbase[NCG], rmbar[NCG];
    #pragma unroll
    for (int r = 0; r < NCG; r++) {
        asm("mapa.shared::cluster.u32 %0, %1, %2;" : "=r"(rbase[r]) : "r"(sWb), "r"(r));
        asm("mapa.shared::cluster.u32 %0, %1, %2;" : "=r"(rmbar[r]) : "r"(mbb), "r"(r));
    }
    const int peer = (lane < 12) ? (lane + (lane >= cg)) : 0;   // warp-0 copy lanes

    // =============== INIT ===============
    if (tid == 0) {
        asm volatile("mbarrier.init.shared.b64 [%0], %1;" :: "r"(mbb),     "r"(1u) : "memory");
        asm volatile("mbarrier.init.shared.b64 [%0], %1;" :: "r"(mbb + 8), "r"(1u) : "memory");
        MBAR_EXPECT_TX(mbb,     TXB);          // arm phase 0, both buffers
        MBAR_EXPECT_TX(mbb + 8, TXB);
    }
    // B fragments (E^T slice) in registers
    uint32_t bfr[KT][4][2];
    #pragma unroll
    for (int kt = 0; kt < KT; kt++) {
        #pragma unroll
        for (int nt = 0; nt < 4; nt++) {
            const int jg = j0 + nh * 32 + nt * 8 + g;
            #pragma unroll
            for (int r = 0; r < 2; r++) {
                const int i0 = kb0 + kt * 16 + 2 * tg + 8 * r;
                float lo = (i0     < S && jg < S) ? __expf(trans[(i0    ) * S + jg]) : 0.f;
                float hi = (i0 + 1 < S && jg < S) ? __expf(trans[(i0 + 1) * S + jg]) : 0.f;
                bfr[kt][nt][r] = pack_bf16x2(lo, hi);
            }
        }
    }
    // full W_0 replica (step 1 needs no exchange)
    for (int idx = tid; idx < MB * (JP / 2); idx += NTHR) {
        int r = idx / (JP / 2), cu = idx % (JP / 2);
        int b = grp * MB + r, ja = 2 * cu, jb = ja + 1;
        float f0 = (ja < S) ? __expf(trans[ja] + em[(size_t)b * NT * S + ja]) : 0.f;
        float f1 = (jb < S) ? __expf(trans[jb] + em[(size_t)b * NT * S + jb]) : 0.f;
        sWu[(cu >> 5) * SLICEU + r * SLOTU + (cu & 31)] = pack_bf16x2(f0, f1);
    }
    // EME[t][j][b] = exp(em[b,t,j])/1024 for own group's batches (striped by cg)
    for (size_t id = (size_t)JP + (size_t)cg * NTHR + tid; id < (size_t)NT * JP;
         id += (size_t)NCG * NTHR) {
        int t = (int)(id / JP), j = (int)(id % JP);
        float4* dst = reinterpret_cast<float4*>(&g_EME[id * NB + grp * MB]);
        if (j < S) {
            #pragma unroll
            for (int q = 0; q < 2; q++) {
                const int b0 = grp * MB + q * 4;
                float4 v;
                v.x = __expf(em[((size_t)(b0 + 0) * NT + t) * S + j]) * INV1024;
                v.y = __expf(em[((size_t)(b0 + 1) * NT + t) * S + j]) * INV1024;
                v.z = __expf(em[((size_t)(b0 + 2) * NT + t) * S + j]) * INV1024;
                v.w = __expf(em[((size_t)(b0 + 3) * NT + t) * S + j]) * INV1024;
                dst[q] = v;
            }
        } else {
            float4 z = {0.f, 0.f, 0.f, 0.f};
            dst[0] = z; dst[1] = z;
        }
    }
    // score gather (warp 7; lane = batch)
    if (w == NWARP - 1) {
        const bool is64 = (tags32[1] == 0);   // int64 high words zero (tags>=3)
        const int b = lane;
        float sc = 0.f;
        for (int t = cta + 1; t < NT; t += NCTA) {
            float m = mask[b * NT + t];
            int cur = is64 ? tags32[(b * NT + t) * 2]     : tags32[b * NT + t];
            int prv = is64 ? tags32[(b * NT + t - 1) * 2] : tags32[b * NT + t - 1];
            sc += (em[((size_t)b * NT + t) * S + cur] + trans[prv * S + cur]) * m;
        }
        if (cta == NCTA - 1) {
            int tag0 = is64 ? tags32[(b * NT) * 2] : tags32[b * NT];
            sc += trans[tag0] + em[(size_t)b * NT * S + tag0];
            float ms = 0.f;
            for (int t = 0; t < NT; t++) ms += mask[b * NT + t];
            int li = (int)ms - 1;
            int lt = is64 ? tags32[(b * NT + li) * 2] : tags32[b * NT + li];
            sc += trans[lt * S + 1];          // last -> EOS
        }
        st_rel(&g_scp[cta][lane], __float_as_uint(sc));
    }
    __syncthreads();
    CLUSTER_SYNC();                            // mbarrier init/arm visible cluster-wide

    int p0 = 0, p1 = 0;                        // per-buffer phase parities
    float mk = mask[b_e * NT + 1];
    float e0 = g_EME[((size_t)1 * JP + j0 + jl_e) * NB + b_e];
    float e1 = g_EME[((size_t)1 * JP + j0 + jl_e + 1) * NB + b_e];

    // =============== MAIN LOOP: 127 dataflow GEMM steps ===============
    for (int t = 1; t < NT; ++t) {
        const int prev = (t - 1) & 1, cur = t & 1;

        if (t >= 2) {                          // wait for W_{t-1} bulk copies
            if (prev == 0) { MBAR_WAIT(mbb,     p0); p0 ^= 1; }
            else           { MBAR_WAIT(mbb + 8, p1); p1 ^= 1; }
            if (tid == 0 && t < NT - 1)        // re-arm this buffer's next phase
                MBAR_EXPECT_TX(mbb + (uint32_t)prev * 8u, TXB);
        }

        // ---- MMA: A rows from local W replica ----
        const uint32_t* Wp = &sWu[prev * BUFU];
        float c[4][4];
        #pragma unroll
        for (int nt = 0; nt < 4; nt++) { c[nt][0]=0.f; c[nt][1]=0.f; c[nt][2]=0.f; c[nt][3]=0.f; }
        #pragma unroll
        for (int kt = 0; kt < KT; kt++) {
            const int idx8 = kq * KT + kt;
            const int base = (idx8 >> 2) * SLICEU + g * SLOTU + (idx8 & 3) * 8 + tg;
            uint32_t a0 = Wp[base];
            uint32_t a2 = Wp[base + 4];
            #pragma unroll
            for (int nt = 0; nt < 4; nt++)
                mma16816(c[nt], a0, 0u, a2, 0u, bfr[kt][nt][0], bfr[kt][nt][1]);
        }
        #pragma unroll
        for (int nt = 0; nt < 4; nt++) {
            float2* p = reinterpret_cast<float2*>(&s_D[kq][g][nh * 32 + nt * 8 + 2 * tg]);
            *p = make_float2(c[nt][0], c[nt][1]);
        }
        __syncthreads();

        // ---- epilogue: reduce k-quarters, scale, pack; stage own slice ----
        {
            float s0 = 0.f, s1 = 0.f;
            #pragma unroll
            for (int q = 0; q < 4; q++) {
                s0 += s_D[q][bl_e][jl_e];
                s1 += s_D[q][bl_e][jl_e + 1];
            }
            float nv0 = s0 * e0, nv1 = s1 * e1;
            if (mk <= 0.f) {                   // masked step: carry old (exact 2^-10)
                uint32_t old = sWu[prev * BUFU + cg * SLICEU + bl_e * SLOTU + jp_e];
                nv0 = __uint_as_float(old << 16)         * INV1024;
                nv1 = __uint_as_float(old & 0xFFFF0000u) * INV1024;
            }
            sWu[cur * BUFU + cg * SLICEU + bl_e * SLOTU + jp_e] = pack_bf16x2(nv0, nv1);
        }
        __syncthreads();                       // staging complete

        // ---- 12 bulk copies (1152 B each) to peers, tx-signaled ----
        if (w == 0 && lane < 12) {
            asm volatile("fence.proxy.async.shared::cta;" ::: "memory");
            const uint32_t so = (uint32_t)(cur * BUFB + cg * SLICEB);
            bulk_copy_cluster(rbase[peer] + so, sWb + so, SLICEB,
                              rmbar[peer] + (uint32_t)cur * 8u);
        }

        if (t + 1 < NT) {                      // prefetch next step's inputs
            mk = mask[b_e * NT + (t + 1)];
            e0 = g_EME[((size_t)(t + 1) * JP + j0 + jl_e) * NB + b_e];
            e1 = g_EME[((size_t)(t + 1) * JP + j0 + jl_e + 1) * NB + b_e];
        }
    }

    // all CTAs consume the final buf1 phase (W_127) -> all engines drained
    MBAR_WAIT(mbb + 8, p1);

    // =============== FINAL: per-group z, then CTA 0 reduces ===============
    if (cg == 0) {
        __syncthreads();
        if (w < MB) {
            float zp = 0.f;                    // warp w -> batch row w
            for (int cu = lane; cu < JP / 2; cu += 32) {
                uint32_t u = sWu[BUFU + (cu >> 5) * SLICEU + w * SLOTU + (cu & 31)];
                int ja = 2 * cu, jb = ja + 1;
                if (ja < S) zp += __uint_as_float(u << 16)         * __expf(trans[ja * S + 1]);
                if (jb < S) zp += __uint_as_float(u & 0xFFFF0000u) * __expf(trans[jb * S + 1]);
            }
            #pragma unroll
            for (int o = 16; o; o >>= 1) zp += __shfl_xor_sync(0xffffffffu, zp, o);
            if (lane == 0) st_rel(&g_zfin[grp * MB + w], __float_as_uint(zp));
        }
        __syncthreads();
        if (tid == 0) st_rel(&g_fin[grp * 32], finbase + 1u);
    }
    CLUSTER_SYNC();                            // no CTA exits with copies in flight

    if (cta == 0) {
        if (tid == 0) {
            for (int gg = 1; gg < NGR; gg++)
                while ((int)(ld_acq(&g_fin[gg * 32]) - (finbase + 1u)) < 0) { }
        }
        __syncthreads();
        if (w == 0) {
            const int b = lane;
            float zs = __uint_as_float(ld_acq(&g_zfin[b]));
            float sc = 0.f;
            for (int c2 = 0; c2 < NCTA; c2++)
                sc += __uint_as_float(ld_acq(&g_scp[c2][b]));
            float r = (logf(zs) + LSUM) - sc;  // log_z - score per batch
            #pragma unroll
            for (int o = 16; o; o >>= 1) r += __shfl_xor_sync(0xffffffffu, r, o);
            if (lane == 0) out[0] = r;         // NLL
        }
    }
}

extern "C" void kernel_launch(void* const* d_in, const int* in_sizes, int n_in,
                              void* d_out, int out_size)
{
    (void)in_sizes; (void)n_in; (void)out_size;
    const float* em    = (const float*)d_in[0];
    const int*   tags  = (const int*)  d_in[1];   // int64 or int32, detected in-kernel
    const float* mask  = (const float*)d_in[2];
    const float* trans = (const float*)d_in[3];
    float* o = (float*)d_out;

    cudaFuncSetAttribute(crf_kernel, cudaFuncAttributeNonPortableClusterSizeAllowed, 1);

    cudaLaunchConfig_t cfg = {};
    cfg.gridDim  = {NCTA, 1, 1};
    cfg.blockDim = {NTHR, 1, 1};
    cfg.dynamicSmemBytes = 0;
    cfg.stream = 0;
    cudaLaunchAttribute at[1];
    at[0].id = cudaLaunchAttributeClusterDimension;
    at[0].val.clusterDim = {NCG, 1, 1};
    cfg.attrs = at;
    cfg.numAttrs = 1;
    cudaLaunchKernelEx(&cfg, crf_kernel, em, tags, mask, trans, o);
}